// round 16
// baseline (speedup 1.0000x reference)
#include <cuda_runtime.h>

// VAE forward, B = 4,000,000 rows. Single kernel, NT=128, 2 rows/thread,
// neuron-pair f32x2 packing (R13 champion: weight pairs (w[j][k],w[j+1][k])
// in shared without duplication, 42 LDS.128/thread per chunk).
// R15 lesson: reg caps always lose (40-reg remat bloat). No min-blocks bound.
// R16 change: 2 chunks per block (#pragma unroll 1 loop) -- weights staged
// once per block instead of once per 256 rows; halves block churn. Chunk-0
// input loads stay hoisted above the staging for DRAM-latency overlap.
//
// Inputs: x[B,8], eps[B,4], w1[6,8], w21[4,6], w22[4,6], w3[6,4], w4[8,6]
// Output: concat(out[B,8], mu[B,4], logvar[B,4]) float32.

#define NT 128
#define CHUNK (2 * NT)      // 256 rows per chunk
#define CPB 2               // chunks per block

typedef unsigned long long u64;

__device__ __forceinline__ u64 pk(float lo, float hi) {
    u64 d; asm("mov.b64 %0,{%1,%2};" : "=l"(d) : "f"(lo), "f"(hi)); return d;
}
__device__ __forceinline__ u64 dup(float v) {
    u64 d; asm("mov.b64 %0,{%1,%1};" : "=l"(d) : "f"(v)); return d;
}
__device__ __forceinline__ void upk(float& lo, float& hi, u64 v) {
    asm("mov.b64 {%0,%1},%2;" : "=f"(lo), "=f"(hi) : "l"(v));
}
__device__ __forceinline__ u64 fma2(u64 a, u64 b, u64 c) {
    u64 d; asm("fma.rn.f32x2 %0,%1,%2,%3;" : "=l"(d) : "l"(a), "l"(b), "l"(c)); return d;
}
__device__ __forceinline__ u64 mul2(u64 a, u64 b) {
    u64 d; asm("mul.rn.f32x2 %0,%1,%2;" : "=l"(d) : "l"(a), "l"(b)); return d;
}
__device__ __forceinline__ void elu_dup(u64 s, u64& dlo, u64& dhi) {
    float lo, hi; upk(lo, hi, s);
    lo = lo > 0.0f ? lo : (__expf(lo) - 1.0f);
    hi = hi > 0.0f ? hi : (__expf(hi) - 1.0f);
    dlo = dup(lo); dhi = dup(hi);
}
// exp(0.5*x) = 2^(x * 0.72134752)
__device__ __forceinline__ float exph(float v) {
    return exp2f(v * 0.72134752044448170368f);
}
__device__ __forceinline__ void stcs2(void* p, u64 a, u64 b) {
    asm volatile("st.global.cs.v2.u64 [%0],{%1,%2};" :: "l"(p), "l"(a), "l"(b) : "memory");
}

// Shared pair layout (u64 index p), pair = (w[2jp][k], w[2jp+1][k]):
//  W1 [0,24) | W21 [24,36) | W22 [36,48) | W3 [48,60) | W4 [60,84)

struct In6 { float4 xa0, xb0, e0, xa1, xb1, e1; };

__device__ __forceinline__ In6 load_in(const float4* __restrict__ x,
                                       const float4* __restrict__ eps,
                                       int i0, int i1, bool v1)
{
    In6 r;
    const float4 z4 = make_float4(0.f, 0.f, 0.f, 0.f);
    r.xa0 = __ldcs(&x[2 * i0]);
    r.xb0 = __ldcs(&x[2 * i0 + 1]);
    r.e0  = __ldcs(&eps[i0]);
    r.xa1 = v1 ? __ldcs(&x[2 * i1])     : z4;
    r.xb1 = v1 ? __ldcs(&x[2 * i1 + 1]) : z4;
    r.e1  = v1 ? __ldcs(&eps[i1])       : z4;
    return r;
}

__device__ __forceinline__ void process(const In6& in, const ulonglong2* sd2,
                                        int i0, int i1, bool v1,
                                        float4* __restrict__ out,
                                        float4* __restrict__ mu_out,
                                        float4* __restrict__ lv_out)
{
    const float xs0[8] = {in.xa0.x, in.xa0.y, in.xa0.z, in.xa0.w,
                          in.xb0.x, in.xb0.y, in.xb0.z, in.xb0.w};
    const float xs1[8] = {in.xa1.x, in.xa1.y, in.xa1.z, in.xa1.w,
                          in.xb1.x, in.xb1.y, in.xb1.z, in.xb1.w};

    // ---- encoder: h1 = elu(x @ w1.T) as dup pairs per row ----
    u64 h1d0[6], h1d1[6];
#pragma unroll
    for (int jp = 0; jp < 3; jp++) {
        const ulonglong2 q0 = sd2[jp * 4 + 0];
        const ulonglong2 q1 = sd2[jp * 4 + 1];
        const ulonglong2 q2 = sd2[jp * 4 + 2];
        const ulonglong2 q3 = sd2[jp * 4 + 3];
        u64 s0 = mul2(dup(xs0[0]), q0.x);
        s0 = fma2(dup(xs0[1]), q0.y, s0);
        s0 = fma2(dup(xs0[2]), q1.x, s0);
        s0 = fma2(dup(xs0[3]), q1.y, s0);
        s0 = fma2(dup(xs0[4]), q2.x, s0);
        s0 = fma2(dup(xs0[5]), q2.y, s0);
        s0 = fma2(dup(xs0[6]), q3.x, s0);
        s0 = fma2(dup(xs0[7]), q3.y, s0);
        elu_dup(s0, h1d0[2 * jp], h1d0[2 * jp + 1]);
        u64 s1 = mul2(dup(xs1[0]), q0.x);
        s1 = fma2(dup(xs1[1]), q0.y, s1);
        s1 = fma2(dup(xs1[2]), q1.x, s1);
        s1 = fma2(dup(xs1[3]), q1.y, s1);
        s1 = fma2(dup(xs1[4]), q2.x, s1);
        s1 = fma2(dup(xs1[5]), q2.y, s1);
        s1 = fma2(dup(xs1[6]), q3.x, s1);
        s1 = fma2(dup(xs1[7]), q3.y, s1);
        elu_dup(s1, h1d1[2 * jp], h1d1[2 * jp + 1]);
    }

    // ---- mu / logvar ----
    u64 mp0[2], mp1[2], lp0[2], lp1[2];
#pragma unroll
    for (int jp = 0; jp < 2; jp++) {
        const ulonglong2 m0 = sd2[12 + jp * 3 + 0];
        const ulonglong2 m1 = sd2[12 + jp * 3 + 1];
        const ulonglong2 m2 = sd2[12 + jp * 3 + 2];
        u64 a0 = mul2(h1d0[0], m0.x);
        a0 = fma2(h1d0[1], m0.y, a0);
        a0 = fma2(h1d0[2], m1.x, a0);
        a0 = fma2(h1d0[3], m1.y, a0);
        a0 = fma2(h1d0[4], m2.x, a0);
        a0 = fma2(h1d0[5], m2.y, a0);
        mp0[jp] = a0;
        u64 a1 = mul2(h1d1[0], m0.x);
        a1 = fma2(h1d1[1], m0.y, a1);
        a1 = fma2(h1d1[2], m1.x, a1);
        a1 = fma2(h1d1[3], m1.y, a1);
        a1 = fma2(h1d1[4], m2.x, a1);
        a1 = fma2(h1d1[5], m2.y, a1);
        mp1[jp] = a1;
        const ulonglong2 l0 = sd2[18 + jp * 3 + 0];
        const ulonglong2 l1 = sd2[18 + jp * 3 + 1];
        const ulonglong2 l2 = sd2[18 + jp * 3 + 2];
        u64 b0 = mul2(h1d0[0], l0.x);
        b0 = fma2(h1d0[1], l0.y, b0);
        b0 = fma2(h1d0[2], l1.x, b0);
        b0 = fma2(h1d0[3], l1.y, b0);
        b0 = fma2(h1d0[4], l2.x, b0);
        b0 = fma2(h1d0[5], l2.y, b0);
        lp0[jp] = b0;
        u64 b1 = mul2(h1d1[0], l0.x);
        b1 = fma2(h1d1[1], l0.y, b1);
        b1 = fma2(h1d1[2], l1.x, b1);
        b1 = fma2(h1d1[3], l1.y, b1);
        b1 = fma2(h1d1[4], l2.x, b1);
        b1 = fma2(h1d1[5], l2.y, b1);
        lp1[jp] = b1;
    }

    stcs2(&mu_out[i0], mp0[0], mp0[1]);
    stcs2(&lv_out[i0], lp0[0], lp0[1]);
    if (v1) {
        stcs2(&mu_out[i1], mp1[0], mp1[1]);
        stcs2(&lv_out[i1], lp1[0], lp1[1]);
    }

    // ---- reparameterize ----
    u64 zd0[4], zd1[4];
    {
        float a, b, c, d;
        upk(a, b, lp0[0]); upk(c, d, lp0[1]);
        const u64 zp0 = fma2(pk(in.e0.x, in.e0.y), pk(exph(a), exph(b)), mp0[0]);
        const u64 zp1 = fma2(pk(in.e0.z, in.e0.w), pk(exph(c), exph(d)), mp0[1]);
        float u, v, w, s;
        upk(u, v, zp0); upk(w, s, zp1);
        zd0[0] = dup(u); zd0[1] = dup(v); zd0[2] = dup(w); zd0[3] = dup(s);
    }
    {
        float a, b, c, d;
        upk(a, b, lp1[0]); upk(c, d, lp1[1]);
        const u64 zp0 = fma2(pk(in.e1.x, in.e1.y), pk(exph(a), exph(b)), mp1[0]);
        const u64 zp1 = fma2(pk(in.e1.z, in.e1.w), pk(exph(c), exph(d)), mp1[1]);
        float u, v, w, s;
        upk(u, v, zp0); upk(w, s, zp1);
        zd1[0] = dup(u); zd1[1] = dup(v); zd1[2] = dup(w); zd1[3] = dup(s);
    }

    // ---- decoder: h3 = elu(z @ w3.T) ----
    u64 h3d0[6], h3d1[6];
#pragma unroll
    for (int jp = 0; jp < 3; jp++) {
        const ulonglong2 q0 = sd2[24 + jp * 2 + 0];
        const ulonglong2 q1 = sd2[24 + jp * 2 + 1];
        u64 s0 = mul2(zd0[0], q0.x);
        s0 = fma2(zd0[1], q0.y, s0);
        s0 = fma2(zd0[2], q1.x, s0);
        s0 = fma2(zd0[3], q1.y, s0);
        elu_dup(s0, h3d0[2 * jp], h3d0[2 * jp + 1]);
        u64 s1 = mul2(zd1[0], q0.x);
        s1 = fma2(zd1[1], q0.y, s1);
        s1 = fma2(zd1[2], q1.x, s1);
        s1 = fma2(zd1[3], q1.y, s1);
        elu_dup(s1, h3d1[2 * jp], h3d1[2 * jp + 1]);
    }

    // ---- out = h3 @ w4.T ----
    u64 op0[4], op1[4];
#pragma unroll
    for (int jp = 0; jp < 4; jp++) {
        const ulonglong2 q0 = sd2[30 + jp * 3 + 0];
        const ulonglong2 q1 = sd2[30 + jp * 3 + 1];
        const ulonglong2 q2 = sd2[30 + jp * 3 + 2];
        u64 s0 = mul2(h3d0[0], q0.x);
        s0 = fma2(h3d0[1], q0.y, s0);
        s0 = fma2(h3d0[2], q1.x, s0);
        s0 = fma2(h3d0[3], q1.y, s0);
        s0 = fma2(h3d0[4], q2.x, s0);
        s0 = fma2(h3d0[5], q2.y, s0);
        op0[jp] = s0;
        u64 s1 = mul2(h3d1[0], q0.x);
        s1 = fma2(h3d1[1], q0.y, s1);
        s1 = fma2(h3d1[2], q1.x, s1);
        s1 = fma2(h3d1[3], q1.y, s1);
        s1 = fma2(h3d1[4], q2.x, s1);
        s1 = fma2(h3d1[5], q2.y, s1);
        op1[jp] = s1;
    }

    stcs2(&out[2 * i0],     op0[0], op0[1]);
    stcs2(&out[2 * i0 + 1], op0[2], op0[3]);
    if (v1) {
        stcs2(&out[2 * i1],     op1[0], op1[1]);
        stcs2(&out[2 * i1 + 1], op1[2], op1[3]);
    }
}

__global__ __launch_bounds__(NT)
void vae_kernel(const float4* __restrict__ x,
                const float4* __restrict__ eps,
                const float* __restrict__ w1,
                const float* __restrict__ w21,
                const float* __restrict__ w22,
                const float* __restrict__ w3,
                const float* __restrict__ w4,
                float4* __restrict__ out,
                float4* __restrict__ mu_out,
                float4* __restrict__ lv_out,
                int B)
{
    __shared__ ulonglong2 sd2[42];

    const int t = threadIdx.x;
    const int base_chunk = blockIdx.x * CPB;

    // ---- chunk 0 loads hoisted above the weight staging (latency overlap) ----
    const int i0 = base_chunk * CHUNK + t;
    const int i1 = i0 + NT;
    const bool v0 = i0 < B;
    const bool v1 = i1 < B;
    In6 cur;
    if (v0) cur = load_in(x, eps, i0, i1, v1);

    // ---- stage neuron-pair weights into shared (once per block) ----
    {
        u64* sf = (u64*)sd2;
        const int p = t;
        if (p < 84) {
            float lo, hi;
            if (p < 24) {
                const int jp = p >> 3, k = p & 7;
                lo = w1[jp * 16 + k];     hi = w1[jp * 16 + 8 + k];
            } else if (p < 36) {
                const int q = p - 24, jp = q / 6, k = q - jp * 6;
                lo = w21[jp * 12 + k];    hi = w21[jp * 12 + 6 + k];
            } else if (p < 48) {
                const int q = p - 36, jp = q / 6, k = q - jp * 6;
                lo = w22[jp * 12 + k];    hi = w22[jp * 12 + 6 + k];
            } else if (p < 60) {
                const int q = p - 48, jp = q >> 2, k = q & 3;
                lo = w3[jp * 8 + k];      hi = w3[jp * 8 + 4 + k];
            } else {
                const int q = p - 60, jp = q / 6, k = q - jp * 6;
                lo = w4[jp * 12 + k];     hi = w4[jp * 12 + 6 + k];
            }
            sf[p] = pk(lo, hi);
        }
    }
    __syncthreads();

    if (v0) process(cur, sd2, i0, i1, v1, out, mu_out, lv_out);

    // ---- remaining chunks (no staging, no sync) ----
#pragma unroll 1
    for (int it = 1; it < CPB; it++) {
        const int j0 = (base_chunk + it) * CHUNK + t;
        const int j1 = j0 + NT;
        if (j0 >= B) break;
        const bool w1v = j1 < B;
        In6 nx = load_in(x, eps, j0, j1, w1v);
        process(nx, sd2, j0, j1, w1v, out, mu_out, lv_out);
    }
}

extern "C" void kernel_launch(void* const* d_in, const int* in_sizes, int n_in,
                              void* d_out, int out_size)
{
    const float4* x   = (const float4*)d_in[0];
    const float4* eps = (const float4*)d_in[1];
    const float*  w1  = (const float*)d_in[2];
    const float*  w21 = (const float*)d_in[3];
    const float*  w22 = (const float*)d_in[4];
    const float*  w3  = (const float*)d_in[5];
    const float*  w4  = (const float*)d_in[6];

    const int B = in_sizes[0] / 8;

    float* outf = (float*)d_out;
    float4* out    = (float4*)outf;
    float4* mu_out = (float4*)(outf + (size_t)B * 8);
    float4* lv_out = (float4*)(outf + (size_t)B * 12);

    const int rows_per_block = CPB * CHUNK;
    const int grid = (B + rows_per_block - 1) / rows_per_block;
    vae_kernel<<<grid, NT>>>(x, eps, w1, w21, w22, w3, w4,
                             out, mu_out, lv_out, B);
}

// round 17
// speedup vs baseline: 1.0335x; 1.0335x over previous
#include <cuda_runtime.h>

// VAE forward, B = 4,000,000 rows. CHAMPION configuration (R13, bench 69.66us):
// single kernel, NT=128, 2 rows/thread, NEURON-PAIR f32x2 packing.
// Each 64-bit lane pair holds two OUTPUT NEURONS (j, j+1) of one row, so
// weight pairs (w[j][k], w[j+1][k]) live in shared WITHOUT duplication and
// each weight register feeds both rows: 42 LDS.128/thread.
// Activation operands are dup pairs (v,v) via mov.b64 {r,r} (CSE-able).
// Epilogue: mu/lv/out pairs are row-major -> st.global.cs.v2.u64.
//
// Verified local optimum: reg caps (R14/R15), NT=96 (R15), multi-chunk (R16),
// prefetch pipelining (R10), persistent blocks (R10), LDCU two-kernel (R5-R9)
// all measured worse or equal. Kernel runs at 75% of HBM spec (~95% of the
// achievable LTS ceiling) on 448MB compulsory traffic.
//
// Inputs: x[B,8], eps[B,4], w1[6,8], w21[4,6], w22[4,6], w3[6,4], w4[8,6]
// Output: concat(out[B,8], mu[B,4], logvar[B,4]) float32.

#define NT 128

typedef unsigned long long u64;

__device__ __forceinline__ u64 pk(float lo, float hi) {
    u64 d; asm("mov.b64 %0,{%1,%2};" : "=l"(d) : "f"(lo), "f"(hi)); return d;
}
__device__ __forceinline__ u64 dup(float v) {
    u64 d; asm("mov.b64 %0,{%1,%1};" : "=l"(d) : "f"(v)); return d;
}
__device__ __forceinline__ void upk(float& lo, float& hi, u64 v) {
    asm("mov.b64 {%0,%1},%2;" : "=f"(lo), "=f"(hi) : "l"(v));
}
__device__ __forceinline__ u64 fma2(u64 a, u64 b, u64 c) {
    u64 d; asm("fma.rn.f32x2 %0,%1,%2,%3;" : "=l"(d) : "l"(a), "l"(b), "l"(c)); return d;
}
__device__ __forceinline__ u64 mul2(u64 a, u64 b) {
    u64 d; asm("mul.rn.f32x2 %0,%1,%2;" : "=l"(d) : "l"(a), "l"(b)); return d;
}
// elu on both lanes, emit each lane as a dup pair for the next layer
__device__ __forceinline__ void elu_dup(u64 s, u64& dlo, u64& dhi) {
    float lo, hi; upk(lo, hi, s);
    lo = lo > 0.0f ? lo : (__expf(lo) - 1.0f);
    hi = hi > 0.0f ? hi : (__expf(hi) - 1.0f);
    dlo = dup(lo); dhi = dup(hi);
}
// exp(0.5*x) = 2^(x * 0.72134752)
__device__ __forceinline__ float exph(float v) {
    return exp2f(v * 0.72134752044448170368f);
}
__device__ __forceinline__ void stcs2(void* p, u64 a, u64 b) {
    asm volatile("st.global.cs.v2.u64 [%0],{%1,%2};" :: "l"(p), "l"(a), "l"(b) : "memory");
}

// Shared pair layout (u64 index p), pair = (w[2jp][k], w[2jp+1][k]):
//  W1  p in [0,24):  jp=p/8 (3), k=p%8
//  W21 p in [24,36): jp=(p-24)/6 (2), k=(p-24)%6
//  W22 p in [36,48): same shape as W21
//  W3  p in [48,60): jp=(p-48)/4 (3), k=(p-48)%4
//  W4  p in [60,84): jp=(p-60)/6 (4), k=(p-60)%6
// ulonglong2 index = p/2; every (matrix, jp) row starts at an even p.

__global__ __launch_bounds__(NT)
void vae_kernel(const float4* __restrict__ x,
                const float4* __restrict__ eps,
                const float* __restrict__ w1,
                const float* __restrict__ w21,
                const float* __restrict__ w22,
                const float* __restrict__ w3,
                const float* __restrict__ w4,
                float4* __restrict__ out,
                float4* __restrict__ mu_out,
                float4* __restrict__ lv_out,
                int B)
{
    __shared__ ulonglong2 sd2[42];

    const int t  = threadIdx.x;
    const int i0 = blockIdx.x * (2 * NT) + t;
    const int i1 = i0 + NT;
    const bool v0 = i0 < B;
    const bool v1 = i1 < B;

    const float4 z4 = make_float4(0.f, 0.f, 0.f, 0.f);

    // ---- issue input loads FIRST (overlap DRAM latency with smem prologue) ----
    float4 xa0 = z4, xb0 = z4, e0 = z4, xa1 = z4, xb1 = z4, e1 = z4;
    if (v0) {
        xa0 = __ldcs(&x[2 * i0]);
        xb0 = __ldcs(&x[2 * i0 + 1]);
        e0  = __ldcs(&eps[i0]);
        if (v1) {
            xa1 = __ldcs(&x[2 * i1]);
            xb1 = __ldcs(&x[2 * i1 + 1]);
            e1  = __ldcs(&eps[i1]);
        }
    }

    // ---- stage neuron-pair weights into shared (no duplication) ----
    {
        u64* sf = (u64*)sd2;
        const int p = t;
        if (p < 84) {
            float lo, hi;
            if (p < 24) {
                const int jp = p >> 3, k = p & 7;
                lo = w1[jp * 16 + k];     hi = w1[jp * 16 + 8 + k];
            } else if (p < 36) {
                const int q = p - 24, jp = q / 6, k = q - jp * 6;
                lo = w21[jp * 12 + k];    hi = w21[jp * 12 + 6 + k];
            } else if (p < 48) {
                const int q = p - 36, jp = q / 6, k = q - jp * 6;
                lo = w22[jp * 12 + k];    hi = w22[jp * 12 + 6 + k];
            } else if (p < 60) {
                const int q = p - 48, jp = q >> 2, k = q & 3;
                lo = w3[jp * 8 + k];      hi = w3[jp * 8 + 4 + k];
            } else {
                const int q = p - 60, jp = q / 6, k = q - jp * 6;
                lo = w4[jp * 12 + k];     hi = w4[jp * 12 + 6 + k];
            }
            sf[p] = pk(lo, hi);
        }
    }
    __syncthreads();

    if (!v0) return;

    const float xs0[8] = {xa0.x, xa0.y, xa0.z, xa0.w, xb0.x, xb0.y, xb0.z, xb0.w};
    const float xs1[8] = {xa1.x, xa1.y, xa1.z, xa1.w, xb1.x, xb1.y, xb1.z, xb1.w};

    // ---- encoder: h1 = elu(x @ w1.T) as dup pairs per row ----
    u64 h1d0[6], h1d1[6];
#pragma unroll
    for (int jp = 0; jp < 3; jp++) {
        const ulonglong2 q0 = sd2[jp * 4 + 0];
        const ulonglong2 q1 = sd2[jp * 4 + 1];
        const ulonglong2 q2 = sd2[jp * 4 + 2];
        const ulonglong2 q3 = sd2[jp * 4 + 3];
        u64 s0 = mul2(dup(xs0[0]), q0.x);
        s0 = fma2(dup(xs0[1]), q0.y, s0);
        s0 = fma2(dup(xs0[2]), q1.x, s0);
        s0 = fma2(dup(xs0[3]), q1.y, s0);
        s0 = fma2(dup(xs0[4]), q2.x, s0);
        s0 = fma2(dup(xs0[5]), q2.y, s0);
        s0 = fma2(dup(xs0[6]), q3.x, s0);
        s0 = fma2(dup(xs0[7]), q3.y, s0);
        elu_dup(s0, h1d0[2 * jp], h1d0[2 * jp + 1]);
        u64 s1 = mul2(dup(xs1[0]), q0.x);
        s1 = fma2(dup(xs1[1]), q0.y, s1);
        s1 = fma2(dup(xs1[2]), q1.x, s1);
        s1 = fma2(dup(xs1[3]), q1.y, s1);
        s1 = fma2(dup(xs1[4]), q2.x, s1);
        s1 = fma2(dup(xs1[5]), q2.y, s1);
        s1 = fma2(dup(xs1[6]), q3.x, s1);
        s1 = fma2(dup(xs1[7]), q3.y, s1);
        elu_dup(s1, h1d1[2 * jp], h1d1[2 * jp + 1]);
    }

    // ---- mu / logvar (neuron pairs: jp=0 -> (mu0,mu1), jp=1 -> (mu2,mu3)) ----
    u64 mp0[2], mp1[2], lp0[2], lp1[2];
#pragma unroll
    for (int jp = 0; jp < 2; jp++) {
        const ulonglong2 m0 = sd2[12 + jp * 3 + 0];
        const ulonglong2 m1 = sd2[12 + jp * 3 + 1];
        const ulonglong2 m2 = sd2[12 + jp * 3 + 2];
        u64 a0 = mul2(h1d0[0], m0.x);
        a0 = fma2(h1d0[1], m0.y, a0);
        a0 = fma2(h1d0[2], m1.x, a0);
        a0 = fma2(h1d0[3], m1.y, a0);
        a0 = fma2(h1d0[4], m2.x, a0);
        a0 = fma2(h1d0[5], m2.y, a0);
        mp0[jp] = a0;
        u64 a1 = mul2(h1d1[0], m0.x);
        a1 = fma2(h1d1[1], m0.y, a1);
        a1 = fma2(h1d1[2], m1.x, a1);
        a1 = fma2(h1d1[3], m1.y, a1);
        a1 = fma2(h1d1[4], m2.x, a1);
        a1 = fma2(h1d1[5], m2.y, a1);
        mp1[jp] = a1;
        const ulonglong2 l0 = sd2[18 + jp * 3 + 0];
        const ulonglong2 l1 = sd2[18 + jp * 3 + 1];
        const ulonglong2 l2 = sd2[18 + jp * 3 + 2];
        u64 b0 = mul2(h1d0[0], l0.x);
        b0 = fma2(h1d0[1], l0.y, b0);
        b0 = fma2(h1d0[2], l1.x, b0);
        b0 = fma2(h1d0[3], l1.y, b0);
        b0 = fma2(h1d0[4], l2.x, b0);
        b0 = fma2(h1d0[5], l2.y, b0);
        lp0[jp] = b0;
        u64 b1 = mul2(h1d1[0], l0.x);
        b1 = fma2(h1d1[1], l0.y, b1);
        b1 = fma2(h1d1[2], l1.x, b1);
        b1 = fma2(h1d1[3], l1.y, b1);
        b1 = fma2(h1d1[4], l2.x, b1);
        b1 = fma2(h1d1[5], l2.y, b1);
        lp1[jp] = b1;
    }

    // ---- stores: pairs are already row-major (mu0,mu1),(mu2,mu3) ----
    stcs2(&mu_out[i0], mp0[0], mp0[1]);
    stcs2(&lv_out[i0], lp0[0], lp0[1]);
    if (v1) {
        stcs2(&mu_out[i1], mp1[0], mp1[1]);
        stcs2(&lv_out[i1], lp1[0], lp1[1]);
    }

    // ---- reparameterize: z = mu + eps * exp(0.5*lv), per row ----
    u64 zd0[4], zd1[4];
    {
        float a, b, c, d;
        upk(a, b, lp0[0]); upk(c, d, lp0[1]);
        const u64 zp0 = fma2(pk(e0.x, e0.y), pk(exph(a), exph(b)), mp0[0]);
        const u64 zp1 = fma2(pk(e0.z, e0.w), pk(exph(c), exph(d)), mp0[1]);
        float u, v, w, s;
        upk(u, v, zp0); upk(w, s, zp1);
        zd0[0] = dup(u); zd0[1] = dup(v); zd0[2] = dup(w); zd0[3] = dup(s);
    }
    {
        float a, b, c, d;
        upk(a, b, lp1[0]); upk(c, d, lp1[1]);
        const u64 zp0 = fma2(pk(e1.x, e1.y), pk(exph(a), exph(b)), mp1[0]);
        const u64 zp1 = fma2(pk(e1.z, e1.w), pk(exph(c), exph(d)), mp1[1]);
        float u, v, w, s;
        upk(u, v, zp0); upk(w, s, zp1);
        zd1[0] = dup(u); zd1[1] = dup(v); zd1[2] = dup(w); zd1[3] = dup(s);
    }

    // ---- decoder: h3 = elu(z @ w3.T) as dup pairs ----
    u64 h3d0[6], h3d1[6];
#pragma unroll
    for (int jp = 0; jp < 3; jp++) {
        const ulonglong2 q0 = sd2[24 + jp * 2 + 0];
        const ulonglong2 q1 = sd2[24 + jp * 2 + 1];
        u64 s0 = mul2(zd0[0], q0.x);
        s0 = fma2(zd0[1], q0.y, s0);
        s0 = fma2(zd0[2], q1.x, s0);
        s0 = fma2(zd0[3], q1.y, s0);
        elu_dup(s0, h3d0[2 * jp], h3d0[2 * jp + 1]);
        u64 s1 = mul2(zd1[0], q0.x);
        s1 = fma2(zd1[1], q0.y, s1);
        s1 = fma2(zd1[2], q1.x, s1);
        s1 = fma2(zd1[3], q1.y, s1);
        elu_dup(s1, h3d1[2 * jp], h3d1[2 * jp + 1]);
    }

    // ---- out = h3 @ w4.T (4 neuron pairs per row = full row, in order) ----
    u64 op0[4], op1[4];
#pragma unroll
    for (int jp = 0; jp < 4; jp++) {
        const ulonglong2 q0 = sd2[30 + jp * 3 + 0];
        const ulonglong2 q1 = sd2[30 + jp * 3 + 1];
        const ulonglong2 q2 = sd2[30 + jp * 3 + 2];
        u64 s0 = mul2(h3d0[0], q0.x);
        s0 = fma2(h3d0[1], q0.y, s0);
        s0 = fma2(h3d0[2], q1.x, s0);
        s0 = fma2(h3d0[3], q1.y, s0);
        s0 = fma2(h3d0[4], q2.x, s0);
        s0 = fma2(h3d0[5], q2.y, s0);
        op0[jp] = s0;
        u64 s1 = mul2(h3d1[0], q0.x);
        s1 = fma2(h3d1[1], q0.y, s1);
        s1 = fma2(h3d1[2], q1.x, s1);
        s1 = fma2(h3d1[3], q1.y, s1);
        s1 = fma2(h3d1[4], q2.x, s1);
        s1 = fma2(h3d1[5], q2.y, s1);
        op1[jp] = s1;
    }

    stcs2(&out[2 * i0],     op0[0], op0[1]);
    stcs2(&out[2 * i0 + 1], op0[2], op0[3]);
    if (v1) {
        stcs2(&out[2 * i1],     op1[0], op1[1]);
        stcs2(&out[2 * i1 + 1], op1[2], op1[3]);
    }
}

extern "C" void kernel_launch(void* const* d_in, const int* in_sizes, int n_in,
                              void* d_out, int out_size)
{
    const float4* x   = (const float4*)d_in[0];
    const float4* eps = (const float4*)d_in[1];
    const float*  w1  = (const float*)d_in[2];
    const float*  w21 = (const float*)d_in[3];
    const float*  w22 = (const float*)d_in[4];
    const float*  w3  = (const float*)d_in[5];
    const float*  w4  = (const float*)d_in[6];

    const int B = in_sizes[0] / 8;

    float* outf = (float*)d_out;
    float4* out    = (float4*)outf;
    float4* mu_out = (float4*)(outf + (size_t)B * 8);
    float4* lv_out = (float4*)(outf + (size_t)B * 12);

    const int rows_per_block = 2 * NT;
    const int grid = (B + rows_per_block - 1) / rows_per_block;
    vae_kernel<<<grid, NT>>>(x, eps, w1, w21, w22, w3, w4,
                             out, mu_out, lv_out, B);
}